// round 13
// baseline (speedup 1.0000x reference)
#include <cuda_runtime.h>
#include <cstdint>

// Problem constants: B=2, H=16, S=2048, D=64
#define SQ   2048
#define DD   64
#define NBH  32      // B*H
#define HPB  16      // heads per batch

// Row stats scratch (softmax max / sum per (bh, q) row). 2 * 256 KB static device mem.
__device__ float g_rowmax[NBH * SQ];
__device__ float g_rowsum[NBH * SQ];

// ---------------- packed f32x2 helpers (FFMA2 path, 2x fp32 FMA throughput) ----
__device__ __forceinline__ unsigned long long pk2(float lo, float hi) {
    unsigned long long r;
    asm("mov.b64 %0, {%1, %2};" : "=l"(r) : "f"(lo), "f"(hi));
    return r;
}
__device__ __forceinline__ void fma2(unsigned long long& d,
                                     unsigned long long a,
                                     unsigned long long b) {
    asm("fma.rn.f32x2 %0, %1, %2, %0;" : "+l"(d) : "l"(a), "l"(b));
}
__device__ __forceinline__ float2 up2(unsigned long long v) {
    float2 f;
    asm("mov.b64 {%0, %1}, %2;" : "=f"(f.x), "=f"(f.y) : "l"(v));
    return f;
}

// =============================================================================
// Kernel 1: scores = (Q @ K^T) * 0.125, masked.  Writes into prob region.
// Block = 64x64 output tile, 256 threads, each thread 4x4 micro-tile.
// K-depth is exactly 64, single smem stage.
// grid: (ktile=32, qtile=32, bh=32)
// =============================================================================
__global__ __launch_bounds__(256) void qk_kernel(
    const float* __restrict__ Q, const float* __restrict__ K,
    const int* __restrict__ mask, float* __restrict__ Sc)
{
    __shared__ float Qs[64][66];   // [k][q]  (transposed; stride 66 keeps 8B align)
    __shared__ float Ks[64][66];   // [k][kcol]

    const int bh = blockIdx.z;
    const int b  = bh / HPB;
    const int q0 = blockIdx.y * 64;
    const int k0 = blockIdx.x * 64;
    const int tx = threadIdx.x, ty = threadIdx.y;
    const int tid = ty * 16 + tx;

    const float* Qb = Q + (size_t)bh * SQ * DD;
    const float* Kb = K + (size_t)bh * SQ * DD;

    // Cooperative load: thread -> row (tid>>2), 16 consecutive cols via 4x float4
    const int lr  = tid >> 2;
    const int lc0 = (tid & 3) * 16;
#pragma unroll
    for (int v = 0; v < 4; v++) {
        const int c = lc0 + v * 4;
        float4 q4 = *(const float4*)(Qb + (size_t)(q0 + lr) * DD + c);
        Qs[c + 0][lr] = q4.x; Qs[c + 1][lr] = q4.y;
        Qs[c + 2][lr] = q4.z; Qs[c + 3][lr] = q4.w;
        float4 k4 = *(const float4*)(Kb + (size_t)(k0 + lr) * DD + c);
        Ks[c + 0][lr] = k4.x; Ks[c + 1][lr] = k4.y;
        Ks[c + 2][lr] = k4.z; Ks[c + 3][lr] = k4.w;
    }
    __syncthreads();

    unsigned long long acc[4][2];
#pragma unroll
    for (int i = 0; i < 4; i++) { acc[i][0] = 0ull; acc[i][1] = 0ull; }

#pragma unroll 16
    for (int kk = 0; kk < 64; kk++) {
        // B operand: 4 contiguous K-cols per thread -> two packed f32x2 loads
        const unsigned long long b0 = *(const unsigned long long*)(&Ks[kk][tx * 4]);
        const unsigned long long b1 = *(const unsigned long long*)(&Ks[kk][tx * 4 + 2]);
#pragma unroll
        for (int i = 0; i < 4; i++) {
            const float a = Qs[kk][ty * 4 + i];
            const unsigned long long ap = pk2(a, a);
            fma2(acc[i][0], ap, b0);
            fma2(acc[i][1], ap, b1);
        }
    }

    // scale + mask + store
    const int* mrow = mask + (size_t)b * SQ * SQ;
    float* Sb = Sc + (size_t)bh * SQ * SQ;
    const int kc = k0 + tx * 4;
#pragma unroll
    for (int i = 0; i < 4; i++) {
        const int q = q0 + ty * 4 + i;
        float2 c0 = up2(acc[i][0]);
        float2 c1 = up2(acc[i][1]);
        float4 r;
        r.x = c0.x * 0.125f; r.y = c0.y * 0.125f;
        r.z = c1.x * 0.125f; r.w = c1.y * 0.125f;
        const int4 m4 = *(const int4*)(mrow + (size_t)q * SQ + kc);
        if (m4.x == 0) r.x = -1e9f;
        if (m4.y == 0) r.y = -1e9f;
        if (m4.z == 0) r.z = -1e9f;
        if (m4.w == 0) r.w = -1e9f;
        *(float4*)(Sb + (size_t)q * SQ + kc) = r;
    }
}

// =============================================================================
// Kernel 2: per-row max and sum(exp(x - max)).  One block (256 thr) per row.
// grid: (NBH*SQ)
// =============================================================================
__global__ __launch_bounds__(256) void rowstats_kernel(const float* __restrict__ Sc)
{
    const int row = blockIdx.x;
    const int tid = threadIdx.x;
    const float4* p = (const float4*)(Sc + (size_t)row * SQ);

    const float4 v0 = p[tid];
    const float4 v1 = p[tid + 256];

    float m = fmaxf(fmaxf(fmaxf(v0.x, v0.y), fmaxf(v0.z, v0.w)),
                    fmaxf(fmaxf(v1.x, v1.y), fmaxf(v1.z, v1.w)));
#pragma unroll
    for (int o = 16; o > 0; o >>= 1)
        m = fmaxf(m, __shfl_xor_sync(0xffffffffu, m, o));

    __shared__ float sm[8];
    __shared__ float ss[8];
    if ((tid & 31) == 0) sm[tid >> 5] = m;
    __syncthreads();
    m = sm[0];
#pragma unroll
    for (int i = 1; i < 8; i++) m = fmaxf(m, sm[i]);

    float s = __expf(v0.x - m) + __expf(v0.y - m) + __expf(v0.z - m) + __expf(v0.w - m)
            + __expf(v1.x - m) + __expf(v1.y - m) + __expf(v1.z - m) + __expf(v1.w - m);
#pragma unroll
    for (int o = 16; o > 0; o >>= 1)
        s += __shfl_xor_sync(0xffffffffu, s, o);
    if ((tid & 31) == 0) ss[tid >> 5] = s;
    __syncthreads();
    if (tid == 0) {
        float t = ss[0];
#pragma unroll
        for (int i = 1; i < 8; i++) t += ss[i];
        g_rowmax[row] = m;
        g_rowsum[row] = t;
    }
}

// =============================================================================
// Kernel 3: read scores, p = exp(s-m)/l, write p back in place (final attn_prob)
// AND accumulate context = P @ V.  Block = 64 queries x full D=64.
// grid: (qtile=32, bh=32)
// =============================================================================
__global__ __launch_bounds__(256) void pv_kernel(
    const float* __restrict__ V, float* __restrict__ P,
    float* __restrict__ ctx)
{
    __shared__ float Ps[64][66];   // [k][q]   (transposed probs)
    __shared__ float Vs[64][68];   // [k][d]   (stride 68 keeps float4 align)

    const int bh = blockIdx.y;
    const int q0 = blockIdx.x * 64;
    const int tx = threadIdx.x, ty = threadIdx.y;
    const int tid = ty * 16 + tx;
    const int lr  = tid >> 2;
    const int lc0 = (tid & 3) * 16;

    const size_t rowbase = (size_t)bh * SQ + q0;
    const float m  = g_rowmax[rowbase + lr];
    const float rl = 1.0f / g_rowsum[rowbase + lr];

    float* Pb = P + (size_t)bh * SQ * SQ;
    const float* Vb = V + (size_t)bh * SQ * DD;

    unsigned long long acc[4][2];
#pragma unroll
    for (int i = 0; i < 4; i++) { acc[i][0] = 0ull; acc[i][1] = 0ull; }

    for (int kt = 0; kt < 32; kt++) {
        const int k0 = kt * 64;
        // Load score tile, transform to prob, write back + stage transposed in smem.
        // Also stage V tile [k][d].
#pragma unroll
        for (int v = 0; v < 4; v++) {
            const int c = lc0 + v * 4;
            float* sp = Pb + (size_t)(q0 + lr) * SQ + k0 + c;
            float4 s4 = *(const float4*)sp;
            float4 p4;
            p4.x = __expf(s4.x - m) * rl;
            p4.y = __expf(s4.y - m) * rl;
            p4.z = __expf(s4.z - m) * rl;
            p4.w = __expf(s4.w - m) * rl;
            *(float4*)sp = p4;                 // final attn_prob output
            Ps[c + 0][lr] = p4.x; Ps[c + 1][lr] = p4.y;
            Ps[c + 2][lr] = p4.z; Ps[c + 3][lr] = p4.w;
            float4 v4 = *(const float4*)(Vb + (size_t)(k0 + lr) * DD + c);
            *(float4*)(&Vs[lr][c]) = v4;
        }
        __syncthreads();

#pragma unroll 16
        for (int kk = 0; kk < 64; kk++) {
            const unsigned long long b0 = *(const unsigned long long*)(&Vs[kk][tx * 4]);
            const unsigned long long b1 = *(const unsigned long long*)(&Vs[kk][tx * 4 + 2]);
#pragma unroll
            for (int i = 0; i < 4; i++) {
                const float a = Ps[kk][ty * 4 + i];
                const unsigned long long ap = pk2(a, a);
                fma2(acc[i][0], ap, b0);
                fma2(acc[i][1], ap, b1);
            }
        }
        __syncthreads();
    }

    float* cb = ctx + (size_t)bh * SQ * DD;
#pragma unroll
    for (int i = 0; i < 4; i++) {
        float2 c0 = up2(acc[i][0]);
        float2 c1 = up2(acc[i][1]);
        float4 r; r.x = c0.x; r.y = c0.y; r.z = c1.x; r.w = c1.y;
        *(float4*)(cb + (size_t)(q0 + ty * 4 + i) * DD + tx * 4) = r;
    }
}

// =============================================================================
// kernel_launch: inputs per metadata order: Q, K, V, attn_mask.
// d_out: [context (B*H*S*D) | attn_prob (B*H*S*S)], float32.
// =============================================================================
extern "C" void kernel_launch(void* const* d_in, const int* in_sizes, int n_in,
                              void* d_out, int out_size)
{
    const float* Q   = (const float*)d_in[0];
    const float* K   = (const float*)d_in[1];
    const float* V   = (const float*)d_in[2];
    const int*   msk = (const int*)d_in[3];

    float* ctx  = (float*)d_out;
    float* prob = (float*)d_out + (size_t)NBH * SQ * DD;

    dim3 blk(16, 16);

    // 1) scores into prob region
    dim3 g1(SQ / 64, SQ / 64, NBH);                  // (32, 32, 32)
    qk_kernel<<<g1, blk>>>(Q, K, msk, prob);

    // 2) per-row max / sumexp
    rowstats_kernel<<<NBH * SQ, 256>>>(prob);

    // 3) normalize in place + context GEMM
    dim3 g3(SQ / 64, NBH);                           // (32, 32)
    pv_kernel<<<g3, blk>>>(V, prob, ctx);
}

// round 14
// speedup vs baseline: 1.0042x; 1.0042x over previous
#include <cuda_runtime.h>
#include <cstdint>

// Problem constants: B=2, H=16, S=2048, D=64
#define SQ   2048
#define DD   64
#define NBH  32      // B*H
#define HPB  16      // heads per batch

// Row stats scratch (softmax max / sum per (bh, q) row). 2 * 256 KB static device mem.
__device__ float g_rowmax[NBH * SQ];
__device__ float g_rowsum[NBH * SQ];

// ---------------- packed f32x2 helpers (FFMA2 path, 2x fp32 FMA throughput) ----
__device__ __forceinline__ unsigned long long pk2(float lo, float hi) {
    unsigned long long r;
    asm("mov.b64 %0, {%1, %2};" : "=l"(r) : "f"(lo), "f"(hi));
    return r;
}
__device__ __forceinline__ void fma2(unsigned long long& d,
                                     unsigned long long a,
                                     unsigned long long b) {
    asm("fma.rn.f32x2 %0, %1, %2, %0;" : "+l"(d) : "l"(a), "l"(b));
}
__device__ __forceinline__ float2 up2(unsigned long long v) {
    float2 f;
    asm("mov.b64 {%0, %1}, %2;" : "=f"(f.x), "=f"(f.y) : "l"(v));
    return f;
}

// =============================================================================
// Kernel 1: scores = (Q @ K^T) * 0.125, masked.  Writes into prob region.
// Block = 64x64 output tile, 256 threads, each thread 4x4 micro-tile.
// K-depth is exactly 64, single smem stage.
// grid: (ktile=32, qtile=32, bh=32)
// =============================================================================
__global__ __launch_bounds__(256) void qk_kernel(
    const float* __restrict__ Q, const float* __restrict__ K,
    const int* __restrict__ mask, float* __restrict__ Sc)
{
    __shared__ float Qs[64][66];   // [k][q]  (transposed; stride 66 keeps 8B align)
    __shared__ float Ks[64][66];   // [k][kcol]

    const int bh = blockIdx.z;
    const int b  = bh / HPB;
    const int q0 = blockIdx.y * 64;
    const int k0 = blockIdx.x * 64;
    const int tx = threadIdx.x, ty = threadIdx.y;
    const int tid = ty * 16 + tx;

    const float* Qb = Q + (size_t)bh * SQ * DD;
    const float* Kb = K + (size_t)bh * SQ * DD;

    // Cooperative load: thread -> row (tid>>2), 16 consecutive cols via 4x float4
    const int lr  = tid >> 2;
    const int lc0 = (tid & 3) * 16;
#pragma unroll
    for (int v = 0; v < 4; v++) {
        const int c = lc0 + v * 4;
        float4 q4 = *(const float4*)(Qb + (size_t)(q0 + lr) * DD + c);
        Qs[c + 0][lr] = q4.x; Qs[c + 1][lr] = q4.y;
        Qs[c + 2][lr] = q4.z; Qs[c + 3][lr] = q4.w;
        float4 k4 = *(const float4*)(Kb + (size_t)(k0 + lr) * DD + c);
        Ks[c + 0][lr] = k4.x; Ks[c + 1][lr] = k4.y;
        Ks[c + 2][lr] = k4.z; Ks[c + 3][lr] = k4.w;
    }
    __syncthreads();

    unsigned long long acc[4][2];
#pragma unroll
    for (int i = 0; i < 4; i++) { acc[i][0] = 0ull; acc[i][1] = 0ull; }

#pragma unroll 16
    for (int kk = 0; kk < 64; kk++) {
        // B operand: 4 contiguous K-cols per thread -> two packed f32x2 loads
        const unsigned long long b0 = *(const unsigned long long*)(&Ks[kk][tx * 4]);
        const unsigned long long b1 = *(const unsigned long long*)(&Ks[kk][tx * 4 + 2]);
#pragma unroll
        for (int i = 0; i < 4; i++) {
            const float a = Qs[kk][ty * 4 + i];
            const unsigned long long ap = pk2(a, a);
            fma2(acc[i][0], ap, b0);
            fma2(acc[i][1], ap, b1);
        }
    }

    // scale + mask + store
    const int* mrow = mask + (size_t)b * SQ * SQ;
    float* Sb = Sc + (size_t)bh * SQ * SQ;
    const int kc = k0 + tx * 4;
#pragma unroll
    for (int i = 0; i < 4; i++) {
        const int q = q0 + ty * 4 + i;
        float2 c0 = up2(acc[i][0]);
        float2 c1 = up2(acc[i][1]);
        float4 r;
        r.x = c0.x * 0.125f; r.y = c0.y * 0.125f;
        r.z = c1.x * 0.125f; r.w = c1.y * 0.125f;
        const int4 m4 = *(const int4*)(mrow + (size_t)q * SQ + kc);
        if (m4.x == 0) r.x = -1e9f;
        if (m4.y == 0) r.y = -1e9f;
        if (m4.z == 0) r.z = -1e9f;
        if (m4.w == 0) r.w = -1e9f;
        *(float4*)(Sb + (size_t)q * SQ + kc) = r;
    }
}

// =============================================================================
// Kernel 2: per-row max and sum(exp(x - max)).  One block (256 thr) per row.
// grid: (NBH*SQ)
// =============================================================================
__global__ __launch_bounds__(256) void rowstats_kernel(const float* __restrict__ Sc)
{
    const int row = blockIdx.x;
    const int tid = threadIdx.x;
    const float4* p = (const float4*)(Sc + (size_t)row * SQ);

    const float4 v0 = p[tid];
    const float4 v1 = p[tid + 256];

    float m = fmaxf(fmaxf(fmaxf(v0.x, v0.y), fmaxf(v0.z, v0.w)),
                    fmaxf(fmaxf(v1.x, v1.y), fmaxf(v1.z, v1.w)));
#pragma unroll
    for (int o = 16; o > 0; o >>= 1)
        m = fmaxf(m, __shfl_xor_sync(0xffffffffu, m, o));

    __shared__ float sm[8];
    __shared__ float ss[8];
    if ((tid & 31) == 0) sm[tid >> 5] = m;
    __syncthreads();
    m = sm[0];
#pragma unroll
    for (int i = 1; i < 8; i++) m = fmaxf(m, sm[i]);

    float s = __expf(v0.x - m) + __expf(v0.y - m) + __expf(v0.z - m) + __expf(v0.w - m)
            + __expf(v1.x - m) + __expf(v1.y - m) + __expf(v1.z - m) + __expf(v1.w - m);
#pragma unroll
    for (int o = 16; o > 0; o >>= 1)
        s += __shfl_xor_sync(0xffffffffu, s, o);
    if ((tid & 31) == 0) ss[tid >> 5] = s;
    __syncthreads();
    if (tid == 0) {
        float t = ss[0];
#pragma unroll
        for (int i = 1; i < 8; i++) t += ss[i];
        g_rowmax[row] = m;
        g_rowsum[row] = t;
    }
}

// =============================================================================
// Kernel 3: read scores, p = exp(s-m)/l, write p back in place (final attn_prob)
// AND accumulate context = P @ V.  Block = 64 queries x full D=64.
// grid: (qtile=32, bh=32)
// =============================================================================
__global__ __launch_bounds__(256) void pv_kernel(
    const float* __restrict__ V, float* __restrict__ P,
    float* __restrict__ ctx)
{
    __shared__ float Ps[64][66];   // [k][q]   (transposed probs)
    __shared__ float Vs[64][68];   // [k][d]   (stride 68 keeps float4 align)

    const int bh = blockIdx.y;
    const int q0 = blockIdx.x * 64;
    const int tx = threadIdx.x, ty = threadIdx.y;
    const int tid = ty * 16 + tx;
    const int lr  = tid >> 2;
    const int lc0 = (tid & 3) * 16;

    const size_t rowbase = (size_t)bh * SQ + q0;
    const float m  = g_rowmax[rowbase + lr];
    const float rl = 1.0f / g_rowsum[rowbase + lr];

    float* Pb = P + (size_t)bh * SQ * SQ;
    const float* Vb = V + (size_t)bh * SQ * DD;

    unsigned long long acc[4][2];
#pragma unroll
    for (int i = 0; i < 4; i++) { acc[i][0] = 0ull; acc[i][1] = 0ull; }

    for (int kt = 0; kt < 32; kt++) {
        const int k0 = kt * 64;
        // Load score tile, transform to prob, write back + stage transposed in smem.
        // Also stage V tile [k][d].
#pragma unroll
        for (int v = 0; v < 4; v++) {
            const int c = lc0 + v * 4;
            float* sp = Pb + (size_t)(q0 + lr) * SQ + k0 + c;
            float4 s4 = *(const float4*)sp;
            float4 p4;
            p4.x = __expf(s4.x - m) * rl;
            p4.y = __expf(s4.y - m) * rl;
            p4.z = __expf(s4.z - m) * rl;
            p4.w = __expf(s4.w - m) * rl;
            *(float4*)sp = p4;                 // final attn_prob output
            Ps[c + 0][lr] = p4.x; Ps[c + 1][lr] = p4.y;
            Ps[c + 2][lr] = p4.z; Ps[c + 3][lr] = p4.w;
            float4 v4 = *(const float4*)(Vb + (size_t)(k0 + lr) * DD + c);
            *(float4*)(&Vs[lr][c]) = v4;
        }
        __syncthreads();

#pragma unroll 16
        for (int kk = 0; kk < 64; kk++) {
            const unsigned long long b0 = *(const unsigned long long*)(&Vs[kk][tx * 4]);
            const unsigned long long b1 = *(const unsigned long long*)(&Vs[kk][tx * 4 + 2]);
#pragma unroll
            for (int i = 0; i < 4; i++) {
                const float a = Ps[kk][ty * 4 + i];
                const unsigned long long ap = pk2(a, a);
                fma2(acc[i][0], ap, b0);
                fma2(acc[i][1], ap, b1);
            }
        }
        __syncthreads();
    }

    float* cb = ctx + (size_t)bh * SQ * DD;
#pragma unroll
    for (int i = 0; i < 4; i++) {
        float2 c0 = up2(acc[i][0]);
        float2 c1 = up2(acc[i][1]);
        float4 r; r.x = c0.x; r.y = c0.y; r.z = c1.x; r.w = c1.y;
        *(float4*)(cb + (size_t)(q0 + ty * 4 + i) * DD + tx * 4) = r;
    }
}

// =============================================================================
// kernel_launch: inputs per metadata order: Q, K, V, attn_mask.
// d_out: [context (B*H*S*D) | attn_prob (B*H*S*S)], float32.
// =============================================================================
extern "C" void kernel_launch(void* const* d_in, const int* in_sizes, int n_in,
                              void* d_out, int out_size)
{
    const float* Q   = (const float*)d_in[0];
    const float* K   = (const float*)d_in[1];
    const float* V   = (const float*)d_in[2];
    const int*   msk = (const int*)d_in[3];

    float* ctx  = (float*)d_out;
    float* prob = (float*)d_out + (size_t)NBH * SQ * DD;

    dim3 blk(16, 16);

    // 1) scores into prob region
    dim3 g1(SQ / 64, SQ / 64, NBH);                  // (32, 32, 32)
    qk_kernel<<<g1, blk>>>(Q, K, msk, prob);

    // 2) per-row max / sumexp
    rowstats_kernel<<<NBH * SQ, 256>>>(prob);

    // 3) normalize in place + context GEMM
    dim3 g3(SQ / 64, NBH);                           // (32, 32)
    pv_kernel<<<g3, blk>>>(V, prob, ctx);
}

// round 15
// speedup vs baseline: 1.3415x; 1.3359x over previous
#include <cuda_runtime.h>
#include <cstdint>

// Problem constants: B=2, H=16, S=2048, D=64
#define SQ   2048
#define DD   64
#define NBH  32      // B*H
#define HPB  16      // heads per batch

// Row stats scratch (softmax max / sum per (bh, q) row).
__device__ float g_rowmax[NBH * SQ];
__device__ float g_rowsum[NBH * SQ];

typedef unsigned long long ull;

// ---------------- packed f32x2 helpers (2x fp32 FMA throughput) ---------------
__device__ __forceinline__ ull pk2(float lo, float hi) {
    ull r;
    asm("mov.b64 %0, {%1, %2};" : "=l"(r) : "f"(lo), "f"(hi));
    return r;
}
__device__ __forceinline__ void fma2(ull& d, ull a, ull b) {
    asm("fma.rn.f32x2 %0, %1, %2, %0;" : "+l"(d) : "l"(a), "l"(b));
}
__device__ __forceinline__ float2 up2(ull v) {
    float2 f;
    asm("mov.b64 {%0, %1}, %2;" : "=f"(f.x), "=f"(f.y) : "l"(v));
    return f;
}

// =============================================================================
// Kernel 1: scores = (Q @ K^T) * 0.125, masked.  Writes into prob region.
// 128x128 tile / block, 256 threads, 8x8 micro-tile per thread.
// D=64 processed in two 32-deep smem stages (static smem < 48KB).
// grid: (ktile=16, qtile=16, bh=32)
// =============================================================================
__global__ __launch_bounds__(256) void qk_kernel(
    const float* __restrict__ Q, const float* __restrict__ K,
    const int* __restrict__ mask, float* __restrict__ Sc)
{
    __shared__ float Qs[32][132];   // [k][q]  transposed; 132*4B = 16B multiple
    __shared__ float Ks[32][132];   // [k][kcol]

    const int bh = blockIdx.z;
    const int b  = bh / HPB;
    const int q0 = blockIdx.y * 128;
    const int k0 = blockIdx.x * 128;
    const int tx = threadIdx.x, ty = threadIdx.y;
    const int tid = ty * 16 + tx;

    const float* Qb = Q + (size_t)bh * SQ * DD;
    const float* Kb = K + (size_t)bh * SQ * DD;

    ull acc[8][4];
#pragma unroll
    for (int i = 0; i < 8; i++)
#pragma unroll
        for (int j = 0; j < 4; j++) acc[i][j] = 0ull;

    // Loader role: threads 0..127 transpose one Q row each; 128..255 one K row.
    const int lrow = tid & 127;
    const float* lsrc_base = (tid < 128)
        ? (Qb + (size_t)(q0 + lrow) * DD)
        : (Kb + (size_t)(k0 + lrow) * DD);
    float (*ldst)[132] = (tid < 128) ? Qs : Ks;

    for (int dh = 0; dh < 2; dh++) {
        if (dh) __syncthreads();
        // Row-per-thread transpose: conflict-free STS (consecutive lanes ->
        // consecutive rows at fixed smem column).
        {
            const float* src = lsrc_base + dh * 32;
#pragma unroll
            for (int v = 0; v < 8; v++) {
                float4 f = *(const float4*)(src + v * 4);
                ldst[v * 4 + 0][lrow] = f.x;
                ldst[v * 4 + 1][lrow] = f.y;
                ldst[v * 4 + 2][lrow] = f.z;
                ldst[v * 4 + 3][lrow] = f.w;
            }
        }
        __syncthreads();

#pragma unroll 4
        for (int kk = 0; kk < 32; kk++) {
            const float4 a0 = *(const float4*)(&Qs[kk][ty * 8]);
            const float4 a1 = *(const float4*)(&Qs[kk][ty * 8 + 4]);
            const ulonglong2 b0 = *(const ulonglong2*)(&Ks[kk][tx * 8]);
            const ulonglong2 b1 = *(const ulonglong2*)(&Ks[kk][tx * 8 + 4]);
            const float av[8] = {a0.x, a0.y, a0.z, a0.w, a1.x, a1.y, a1.z, a1.w};
#pragma unroll
            for (int i = 0; i < 8; i++) {
                const ull ap = pk2(av[i], av[i]);
                fma2(acc[i][0], ap, b0.x);
                fma2(acc[i][1], ap, b0.y);
                fma2(acc[i][2], ap, b1.x);
                fma2(acc[i][3], ap, b1.y);
            }
        }
    }

    // scale + mask + store
    const int* mb = mask + (size_t)b * SQ * SQ;
    float* Sb = Sc + (size_t)bh * SQ * SQ;
    const int kc = k0 + tx * 8;
#pragma unroll
    for (int i = 0; i < 8; i++) {
        const int q = q0 + ty * 8 + i;
        const float2 c0 = up2(acc[i][0]);
        const float2 c1 = up2(acc[i][1]);
        const float2 c2 = up2(acc[i][2]);
        const float2 c3 = up2(acc[i][3]);
        float4 r0, r1;
        r0.x = c0.x * 0.125f; r0.y = c0.y * 0.125f;
        r0.z = c1.x * 0.125f; r0.w = c1.y * 0.125f;
        r1.x = c2.x * 0.125f; r1.y = c2.y * 0.125f;
        r1.z = c3.x * 0.125f; r1.w = c3.y * 0.125f;
        const int4 m0 = *(const int4*)(mb + (size_t)q * SQ + kc);
        const int4 m1 = *(const int4*)(mb + (size_t)q * SQ + kc + 4);
        if (m0.x == 0) r0.x = -1e9f;
        if (m0.y == 0) r0.y = -1e9f;
        if (m0.z == 0) r0.z = -1e9f;
        if (m0.w == 0) r0.w = -1e9f;
        if (m1.x == 0) r1.x = -1e9f;
        if (m1.y == 0) r1.y = -1e9f;
        if (m1.z == 0) r1.z = -1e9f;
        if (m1.w == 0) r1.w = -1e9f;
        *(float4*)(Sb + (size_t)q * SQ + kc)     = r0;
        *(float4*)(Sb + (size_t)q * SQ + kc + 4) = r1;
    }
}

// =============================================================================
// Kernel 2: per-row max and sum(exp(x - max)).  One block (256 thr) per row.
// =============================================================================
__global__ __launch_bounds__(256) void rowstats_kernel(const float* __restrict__ Sc)
{
    const int row = blockIdx.x;
    const int tid = threadIdx.x;
    const float4* p = (const float4*)(Sc + (size_t)row * SQ);

    const float4 v0 = p[tid];
    const float4 v1 = p[tid + 256];

    float m = fmaxf(fmaxf(fmaxf(v0.x, v0.y), fmaxf(v0.z, v0.w)),
                    fmaxf(fmaxf(v1.x, v1.y), fmaxf(v1.z, v1.w)));
#pragma unroll
    for (int o = 16; o > 0; o >>= 1)
        m = fmaxf(m, __shfl_xor_sync(0xffffffffu, m, o));

    __shared__ float sm[8];
    __shared__ float ss[8];
    if ((tid & 31) == 0) sm[tid >> 5] = m;
    __syncthreads();
    m = sm[0];
#pragma unroll
    for (int i = 1; i < 8; i++) m = fmaxf(m, sm[i]);

    float s = __expf(v0.x - m) + __expf(v0.y - m) + __expf(v0.z - m) + __expf(v0.w - m)
            + __expf(v1.x - m) + __expf(v1.y - m) + __expf(v1.z - m) + __expf(v1.w - m);
#pragma unroll
    for (int o = 16; o > 0; o >>= 1)
        s += __shfl_xor_sync(0xffffffffu, s, o);
    if ((tid & 31) == 0) ss[tid >> 5] = s;
    __syncthreads();
    if (tid == 0) {
        float t = ss[0];
#pragma unroll
        for (int i = 1; i < 8; i++) t += ss[i];
        g_rowmax[row] = m;
        g_rowsum[row] = t;
    }
}

// =============================================================================
// Kernel 3: p = exp(s-m)/l written back in place (final attn_prob)
// AND context = P @ V.  128 queries x D=64 per block, 8x4 micro-tile.
// K processed in 64 tiles of 32.  grid: (qtile=16, bh=32)
// =============================================================================
__global__ __launch_bounds__(256) void pv_kernel(
    const float* __restrict__ V, float* __restrict__ P,
    float* __restrict__ ctx)
{
    __shared__ float Ps[32][132];   // [k][q]  transposed probs
    __shared__ float Vs[32][64];    // [k][d]  natural (flat copy, contiguous gmem)

    const int bh = blockIdx.y;
    const int q0 = blockIdx.x * 128;
    const int tx = threadIdx.x, ty = threadIdx.y;
    const int tid = ty * 16 + tx;

    float* Pb = P + (size_t)bh * SQ * SQ;
    const float* Vb = V + (size_t)bh * SQ * DD;

    // Staging role: thread handles row sr (0..127), 16-col chunk sc.
    const int sr = tid >> 1;
    const int sc = (tid & 1) * 16;
    const float sm  = g_rowmax[(size_t)bh * SQ + q0 + sr];
    const float srl = 1.0f / g_rowsum[(size_t)bh * SQ + q0 + sr];

    ull acc[8][2];
#pragma unroll
    for (int i = 0; i < 8; i++) { acc[i][0] = 0ull; acc[i][1] = 0ull; }

    for (int kt = 0; kt < 64; kt++) {
        const int k0 = kt * 32;
        if (kt) __syncthreads();

        // Stage P tile: load scores, softmax transform, write final prob
        // back to gmem, and store transposed into smem.
        {
            float* prow = Pb + (size_t)(q0 + sr) * SQ + k0 + sc;
#pragma unroll
            for (int v = 0; v < 4; v++) {
                float4 s4 = *(const float4*)(prow + v * 4);
                float4 p4;
                p4.x = __expf(s4.x - sm) * srl;
                p4.y = __expf(s4.y - sm) * srl;
                p4.z = __expf(s4.z - sm) * srl;
                p4.w = __expf(s4.w - sm) * srl;
                *(float4*)(prow + v * 4) = p4;           // final attn_prob
                const int c = sc + v * 4;
                Ps[c + 0][sr] = p4.x;
                Ps[c + 1][sr] = p4.y;
                Ps[c + 2][sr] = p4.z;
                Ps[c + 3][sr] = p4.w;
            }
        }
        // Stage V tile: 32x64 floats = contiguous 8KB block -> flat copy.
        {
            const float4* vsrc = (const float4*)(Vb + (size_t)k0 * DD);
            float4* vdst = (float4*)(&Vs[0][0]);
            vdst[tid]       = vsrc[tid];
            vdst[tid + 256] = vsrc[tid + 256];
        }
        __syncthreads();

#pragma unroll 4
        for (int kk = 0; kk < 32; kk++) {
            const float4 a0 = *(const float4*)(&Ps[kk][ty * 8]);
            const float4 a1 = *(const float4*)(&Ps[kk][ty * 8 + 4]);
            const ulonglong2 bb = *(const ulonglong2*)(&Vs[kk][tx * 4]);
            const float av[8] = {a0.x, a0.y, a0.z, a0.w, a1.x, a1.y, a1.z, a1.w};
#pragma unroll
            for (int i = 0; i < 8; i++) {
                const ull ap = pk2(av[i], av[i]);
                fma2(acc[i][0], ap, bb.x);
                fma2(acc[i][1], ap, bb.y);
            }
        }
    }

    float* cb = ctx + (size_t)bh * SQ * DD;
#pragma unroll
    for (int i = 0; i < 8; i++) {
        const float2 c0 = up2(acc[i][0]);
        const float2 c1 = up2(acc[i][1]);
        float4 r;
        r.x = c0.x; r.y = c0.y; r.z = c1.x; r.w = c1.y;
        *(float4*)(cb + (size_t)(q0 + ty * 8 + i) * DD + tx * 4) = r;
    }
}

// =============================================================================
// kernel_launch: inputs Q, K, V, attn_mask.
// d_out: [context (B*H*S*D) | attn_prob (B*H*S*S)], float32.
// =============================================================================
extern "C" void kernel_launch(void* const* d_in, const int* in_sizes, int n_in,
                              void* d_out, int out_size)
{
    const float* Q   = (const float*)d_in[0];
    const float* K   = (const float*)d_in[1];
    const float* V   = (const float*)d_in[2];
    const int*   msk = (const int*)d_in[3];

    float* ctx  = (float*)d_out;
    float* prob = (float*)d_out + (size_t)NBH * SQ * DD;

    dim3 blk(16, 16);

    // 1) scores into prob region
    dim3 g1(SQ / 128, SQ / 128, NBH);                // (16, 16, 32)
    qk_kernel<<<g1, blk>>>(Q, K, msk, prob);

    // 2) per-row max / sumexp
    rowstats_kernel<<<NBH * SQ, 256>>>(prob);

    // 3) normalize in place + context GEMM
    dim3 g3(SQ / 128, NBH);                          // (16, 32)
    pv_kernel<<<g3, blk>>>(V, prob, ctx);
}

// round 16
// speedup vs baseline: 1.3428x; 1.0010x over previous
#include <cuda_runtime.h>
#include <cstdint>

// Problem constants: B=2, H=16, S=2048, D=64
#define SQ   2048
#define DD   64
#define NBH  32      // B*H
#define HPB  16      // heads per batch

// Row stats scratch (softmax max / sum per (bh, q) row).
__device__ float g_rowmax[NBH * SQ];
__device__ float g_rowsum[NBH * SQ];

typedef unsigned long long ull;

// ---------------- packed f32x2 helpers (2x fp32 FMA throughput) ---------------
__device__ __forceinline__ ull pk2(float lo, float hi) {
    ull r;
    asm("mov.b64 %0, {%1, %2};" : "=l"(r) : "f"(lo), "f"(hi));
    return r;
}
__device__ __forceinline__ void fma2(ull& d, ull a, ull b) {
    asm("fma.rn.f32x2 %0, %1, %2, %0;" : "+l"(d) : "l"(a), "l"(b));
}
__device__ __forceinline__ float2 up2(ull v) {
    float2 f;
    asm("mov.b64 {%0, %1}, %2;" : "=f"(f.x), "=f"(f.y) : "l"(v));
    return f;
}

// =============================================================================
// Kernel 1: scores = (Q @ K^T) * 0.125, masked.  Writes into prob region.
// 128x128 tile / block, 256 threads, 8x8 micro-tile per thread.
// D=64 processed in two 32-deep smem stages (static smem < 48KB).
// grid: (ktile=16, qtile=16, bh=32)
// =============================================================================
__global__ __launch_bounds__(256) void qk_kernel(
    const float* __restrict__ Q, const float* __restrict__ K,
    const int* __restrict__ mask, float* __restrict__ Sc)
{
    __shared__ float Qs[32][132];   // [k][q]  transposed; 132*4B = 16B multiple
    __shared__ float Ks[32][132];   // [k][kcol]

    const int bh = blockIdx.z;
    const int b  = bh / HPB;
    const int q0 = blockIdx.y * 128;
    const int k0 = blockIdx.x * 128;
    const int tx = threadIdx.x, ty = threadIdx.y;
    const int tid = ty * 16 + tx;

    const float* Qb = Q + (size_t)bh * SQ * DD;
    const float* Kb = K + (size_t)bh * SQ * DD;

    ull acc[8][4];
#pragma unroll
    for (int i = 0; i < 8; i++)
#pragma unroll
        for (int j = 0; j < 4; j++) acc[i][j] = 0ull;

    // Loader role: threads 0..127 transpose one Q row each; 128..255 one K row.
    const int lrow = tid & 127;
    const float* lsrc_base = (tid < 128)
        ? (Qb + (size_t)(q0 + lrow) * DD)
        : (Kb + (size_t)(k0 + lrow) * DD);
    float (*ldst)[132] = (tid < 128) ? Qs : Ks;

    for (int dh = 0; dh < 2; dh++) {
        if (dh) __syncthreads();
        // Row-per-thread transpose: conflict-free STS (consecutive lanes ->
        // consecutive rows at fixed smem column).
        {
            const float* src = lsrc_base + dh * 32;
#pragma unroll
            for (int v = 0; v < 8; v++) {
                float4 f = *(const float4*)(src + v * 4);
                ldst[v * 4 + 0][lrow] = f.x;
                ldst[v * 4 + 1][lrow] = f.y;
                ldst[v * 4 + 2][lrow] = f.z;
                ldst[v * 4 + 3][lrow] = f.w;
            }
        }
        __syncthreads();

#pragma unroll 4
        for (int kk = 0; kk < 32; kk++) {
            const float4 a0 = *(const float4*)(&Qs[kk][ty * 8]);
            const float4 a1 = *(const float4*)(&Qs[kk][ty * 8 + 4]);
            const ulonglong2 b0 = *(const ulonglong2*)(&Ks[kk][tx * 8]);
            const ulonglong2 b1 = *(const ulonglong2*)(&Ks[kk][tx * 8 + 4]);
            const float av[8] = {a0.x, a0.y, a0.z, a0.w, a1.x, a1.y, a1.z, a1.w};
#pragma unroll
            for (int i = 0; i < 8; i++) {
                const ull ap = pk2(av[i], av[i]);
                fma2(acc[i][0], ap, b0.x);
                fma2(acc[i][1], ap, b0.y);
                fma2(acc[i][2], ap, b1.x);
                fma2(acc[i][3], ap, b1.y);
            }
        }
    }

    // scale + mask + store
    const int* mb = mask + (size_t)b * SQ * SQ;
    float* Sb = Sc + (size_t)bh * SQ * SQ;
    const int kc = k0 + tx * 8;
#pragma unroll
    for (int i = 0; i < 8; i++) {
        const int q = q0 + ty * 8 + i;
        const float2 c0 = up2(acc[i][0]);
        const float2 c1 = up2(acc[i][1]);
        const float2 c2 = up2(acc[i][2]);
        const float2 c3 = up2(acc[i][3]);
        float4 r0, r1;
        r0.x = c0.x * 0.125f; r0.y = c0.y * 0.125f;
        r0.z = c1.x * 0.125f; r0.w = c1.y * 0.125f;
        r1.x = c2.x * 0.125f; r1.y = c2.y * 0.125f;
        r1.z = c3.x * 0.125f; r1.w = c3.y * 0.125f;
        const int4 m0 = *(const int4*)(mb + (size_t)q * SQ + kc);
        const int4 m1 = *(const int4*)(mb + (size_t)q * SQ + kc + 4);
        if (m0.x == 0) r0.x = -1e9f;
        if (m0.y == 0) r0.y = -1e9f;
        if (m0.z == 0) r0.z = -1e9f;
        if (m0.w == 0) r0.w = -1e9f;
        if (m1.x == 0) r1.x = -1e9f;
        if (m1.y == 0) r1.y = -1e9f;
        if (m1.z == 0) r1.z = -1e9f;
        if (m1.w == 0) r1.w = -1e9f;
        *(float4*)(Sb + (size_t)q * SQ + kc)     = r0;
        *(float4*)(Sb + (size_t)q * SQ + kc + 4) = r1;
    }
}

// =============================================================================
// Kernel 2: per-row max and sum(exp(x - max)).  One block (256 thr) per row.
// =============================================================================
__global__ __launch_bounds__(256) void rowstats_kernel(const float* __restrict__ Sc)
{
    const int row = blockIdx.x;
    const int tid = threadIdx.x;
    const float4* p = (const float4*)(Sc + (size_t)row * SQ);

    const float4 v0 = p[tid];
    const float4 v1 = p[tid + 256];

    float m = fmaxf(fmaxf(fmaxf(v0.x, v0.y), fmaxf(v0.z, v0.w)),
                    fmaxf(fmaxf(v1.x, v1.y), fmaxf(v1.z, v1.w)));
#pragma unroll
    for (int o = 16; o > 0; o >>= 1)
        m = fmaxf(m, __shfl_xor_sync(0xffffffffu, m, o));

    __shared__ float sm[8];
    __shared__ float ss[8];
    if ((tid & 31) == 0) sm[tid >> 5] = m;
    __syncthreads();
    m = sm[0];
#pragma unroll
    for (int i = 1; i < 8; i++) m = fmaxf(m, sm[i]);

    float s = __expf(v0.x - m) + __expf(v0.y - m) + __expf(v0.z - m) + __expf(v0.w - m)
            + __expf(v1.x - m) + __expf(v1.y - m) + __expf(v1.z - m) + __expf(v1.w - m);
#pragma unroll
    for (int o = 16; o > 0; o >>= 1)
        s += __shfl_xor_sync(0xffffffffu, s, o);
    if ((tid & 31) == 0) ss[tid >> 5] = s;
    __syncthreads();
    if (tid == 0) {
        float t = ss[0];
#pragma unroll
        for (int i = 1; i < 8; i++) t += ss[i];
        g_rowmax[row] = m;
        g_rowsum[row] = t;
    }
}

// =============================================================================
// Kernel 3: p = exp(s-m)/l written back in place (final attn_prob)
// AND context = P @ V.  128 queries x D=64 per block, 8x4 micro-tile.
// K processed in 64 tiles of 32.  grid: (qtile=16, bh=32)
// =============================================================================
__global__ __launch_bounds__(256) void pv_kernel(
    const float* __restrict__ V, float* __restrict__ P,
    float* __restrict__ ctx)
{
    __shared__ float Ps[32][132];   // [k][q]  transposed probs
    __shared__ float Vs[32][64];    // [k][d]  natural (flat copy, contiguous gmem)

    const int bh = blockIdx.y;
    const int q0 = blockIdx.x * 128;
    const int tx = threadIdx.x, ty = threadIdx.y;
    const int tid = ty * 16 + tx;

    float* Pb = P + (size_t)bh * SQ * SQ;
    const float* Vb = V + (size_t)bh * SQ * DD;

    // Staging role: thread handles row sr (0..127), 16-col chunk sc.
    const int sr = tid >> 1;
    const int sc = (tid & 1) * 16;
    const float sm  = g_rowmax[(size_t)bh * SQ + q0 + sr];
    const float srl = 1.0f / g_rowsum[(size_t)bh * SQ + q0 + sr];

    ull acc[8][2];
#pragma unroll
    for (int i = 0; i < 8; i++) { acc[i][0] = 0ull; acc[i][1] = 0ull; }

    for (int kt = 0; kt < 64; kt++) {
        const int k0 = kt * 32;
        if (kt) __syncthreads();

        // Stage P tile: load scores, softmax transform, write final prob
        // back to gmem, and store transposed into smem.
        {
            float* prow = Pb + (size_t)(q0 + sr) * SQ + k0 + sc;
#pragma unroll
            for (int v = 0; v < 4; v++) {
                float4 s4 = *(const float4*)(prow + v * 4);
                float4 p4;
                p4.x = __expf(s4.x - sm) * srl;
                p4.y = __expf(s4.y - sm) * srl;
                p4.z = __expf(s4.z - sm) * srl;
                p4.w = __expf(s4.w - sm) * srl;
                *(float4*)(prow + v * 4) = p4;           // final attn_prob
                const int c = sc + v * 4;
                Ps[c + 0][sr] = p4.x;
                Ps[c + 1][sr] = p4.y;
                Ps[c + 2][sr] = p4.z;
                Ps[c + 3][sr] = p4.w;
            }
        }
        // Stage V tile: 32x64 floats = contiguous 8KB block -> flat copy.
        {
            const float4* vsrc = (const float4*)(Vb + (size_t)k0 * DD);
            float4* vdst = (float4*)(&Vs[0][0]);
            vdst[tid]       = vsrc[tid];
            vdst[tid + 256] = vsrc[tid + 256];
        }
        __syncthreads();

#pragma unroll 4
        for (int kk = 0; kk < 32; kk++) {
            const float4 a0 = *(const float4*)(&Ps[kk][ty * 8]);
            const float4 a1 = *(const float4*)(&Ps[kk][ty * 8 + 4]);
            const ulonglong2 bb = *(const ulonglong2*)(&Vs[kk][tx * 4]);
            const float av[8] = {a0.x, a0.y, a0.z, a0.w, a1.x, a1.y, a1.z, a1.w};
#pragma unroll
            for (int i = 0; i < 8; i++) {
                const ull ap = pk2(av[i], av[i]);
                fma2(acc[i][0], ap, bb.x);
                fma2(acc[i][1], ap, bb.y);
            }
        }
    }

    float* cb = ctx + (size_t)bh * SQ * DD;
#pragma unroll
    for (int i = 0; i < 8; i++) {
        const float2 c0 = up2(acc[i][0]);
        const float2 c1 = up2(acc[i][1]);
        float4 r;
        r.x = c0.x; r.y = c0.y; r.z = c1.x; r.w = c1.y;
        *(float4*)(cb + (size_t)(q0 + ty * 8 + i) * DD + tx * 4) = r;
    }
}

// =============================================================================
// kernel_launch: inputs Q, K, V, attn_mask.
// d_out: [context (B*H*S*D) | attn_prob (B*H*S*S)], float32.
// =============================================================================
extern "C" void kernel_launch(void* const* d_in, const int* in_sizes, int n_in,
                              void* d_out, int out_size)
{
    const float* Q   = (const float*)d_in[0];
    const float* K   = (const float*)d_in[1];
    const float* V   = (const float*)d_in[2];
    const int*   msk = (const int*)d_in[3];

    float* ctx  = (float*)d_out;
    float* prob = (float*)d_out + (size_t)NBH * SQ * DD;

    dim3 blk(16, 16);

    // 1) scores into prob region
    dim3 g1(SQ / 128, SQ / 128, NBH);                // (16, 16, 32)
    qk_kernel<<<g1, blk>>>(Q, K, msk, prob);

    // 2) per-row max / sumexp
    rowstats_kernel<<<NBH * SQ, 256>>>(prob);

    // 3) normalize in place + context GEMM
    dim3 g3(SQ / 128, NBH);                          // (16, 32)
    pv_kernel<<<g3, blk>>>(V, prob, ctx);
}